// round 12
// baseline (speedup 1.0000x reference)
#include <cuda_runtime.h>

// OpenLSTM: B=4096 sequences, T=1024, HID=16, PROJ=2.
// t < 256 teacher-forced; t >= 256 recurrent.
//
// R12 = R5 (191.5us best) +
//  (a) warp desync after teacher phase: (gwid%4)*112cyc serial-FMA delay to
//      break the MIO/FMA convoy (model: all warps at same PC burst 45 MIO ops
//      together -> step = FMA-section 170 + MIO-section 210 SERIALLY = 382;
//      staggered warps overlap the sections).
//  (b) teacher reduction 8->5 SHFL (segregate + tree + broadcast), lane-0
//      float2 store kept (R11's all-lane same-address stores regressed).
// Recurrent loop byte-identical to R5. TPE=16, 2048 warps.

#define T_TOTAL 1024
#define N_CTX   256
#define TPE     16
#define EPB     4     // elements per 64-thread block
#define TU      4     // teacher-phase time unroll

__device__ __forceinline__ float tanh_fast(float x) {
    float y;
    asm("tanh.approx.f32 %0, %1;" : "=f"(y) : "f"(x));
    return y;
}

__global__ void __launch_bounds__(64)
open_lstm_kernel(const float* __restrict__ u,     // (B, T, 4)
                 const float* __restrict__ w_ih,  // (64, 2)
                 const float* __restrict__ w_hh,  // (64, 2)
                 const float* __restrict__ b_ih,  // (64)
                 const float* __restrict__ b_hh,  // (64)
                 const float* __restrict__ w_hr,  // (2, 16)
                 float* __restrict__ out)         // (B, T, 2)
{
    const int tid  = threadIdx.x;
    const int j    = tid & (TPE - 1);                 // hidden unit 0..15
    const int e    = blockIdx.x * EPB + (tid >> 4);   // element index
    const bool lo8 = (j < 8);

    // Weights for unit j. sigma(x)=0.5*tanh(0.5x)+0.5 folded: i/f/o gate rows
    // pre-scaled by 0.5; o-path outer 0.5 folded into w_hr.
    float wi[4][2], wh[4][2], bb[4], wr0, wr1;
#pragma unroll
    for (int k = 0; k < 4; k++) {
        const int r = k * 16 + j;
        const float sc = (k == 2) ? 1.0f : 0.5f;
        wi[k][0] = w_ih[r * 2 + 0] * sc;
        wi[k][1] = w_ih[r * 2 + 1] * sc;
        wh[k][0] = w_hh[r * 2 + 0] * sc;
        wh[k][1] = w_hh[r * 2 + 1] * sc;
        bb[k]    = (b_ih[r] + b_hh[r]) * sc;
    }
    wr0 = w_hr[j]      * 0.5f;
    wr1 = w_hr[16 + j] * 0.5f;

    const float4* __restrict__ up = (const float4*)u + (size_t)e * T_TOTAL;
    float2* __restrict__ op       = (float2*)out + (size_t)e * T_TOTAL;

    float c = 0.0f, h0 = 0.0f, h1 = 0.0f;

    // ================= teacher-forced phase, unrolled x4 =================
    // 5 SHFL/step: segregate + 3-round tree + broadcast (MIO-bound phase,
    // chain hidden by TU=4 batching).
#pragma unroll 1
    for (int t = 0; t < N_CTX; t += TU) {
        float4 vv[TU];
#pragma unroll
        for (int s = 0; s < TU; s++) vv[s] = up[t + s];

        float gg[TU][4];
#pragma unroll
        for (int s = 0; s < TU; s++)
#pragma unroll
            for (int k = 0; k < 4; k++)
                gg[s][k] = fmaf(wi[k][0], vv[s].x,
                           fmaf(wi[k][1], vv[s].y,
                           fmaf(wh[k][0], vv[s].z,
                           fmaf(wh[k][1], vv[s].w, bb[k]))));

        float ti[TU], tf[TU], tg[TU], to[TU];
#pragma unroll
        for (int s = 0; s < TU; s++) {
            ti[s] = tanh_fast(gg[s][0]);
            tf[s] = tanh_fast(gg[s][1]);
            tg[s] = tanh_fast(gg[s][2]);
            to[s] = tanh_fast(gg[s][3]);
        }

        float tc[TU];
#pragma unroll
        for (int s = 0; s < TU; s++) {
            float ca = fmaf(tf[s], c, c);            // 2*sigma(f)*c
            float cb = fmaf(ti[s], tg[s], tg[s]);    // 2*sigma(i)*tanh(g)
            c = fmaf(0.5f, ca, 0.5f * cb);
            tc[s] = tanh_fast(c);
        }

        float h0v[TU], h1v[TU];
#pragma unroll
        for (int s = 0; s < TU; s++) {
            float b0 = fmaf(wr0, to[s], wr0);        // wr0*(1+to)
            float b1 = fmaf(wr1, to[s], wr1);
            float p0 = b0 * tc[s];
            float p1 = b1 * tc[s];
            // segregate: lanes<8 accumulate p0, lanes>=8 accumulate p1
            float send = lo8 ? p1 : p0;
            float keep = lo8 ? p0 : p1;
            float r = keep + __shfl_xor_sync(0xffffffffu, send, 8);
            r += __shfl_xor_sync(0xffffffffu, r, 1);
            r += __shfl_xor_sync(0xffffffffu, r, 2);
            r += __shfl_xor_sync(0xffffffffu, r, 4);
            float o2 = __shfl_xor_sync(0xffffffffu, r, 8);
            h0v[s] = lo8 ? r : o2;
            h1v[s] = lo8 ? o2 : r;
        }
        if (j == 0) {
#pragma unroll
            for (int s = 0; s < TU; s++)
                op[t + s] = make_float2(h0v[s], h1v[s]);
        }
        h0 = h0v[TU - 1];
        h1 = h1v[TU - 1];
    }

    // ---- warp desynchronization: stagger warps by (gwid%4)*~112 cyc so the
    // recurrent phase's MIO bursts (TANH+SHFL) of different warps overlap the
    // FMA sections of others instead of convoying at the same PC.
    {
        int gwid = ((int)blockIdx.x * 2 + (tid >> 5)) & 3;
        float dly = (float)tid;
        for (int i = 0; i < gwid * 28; i++)          // 28 serial FMA = ~112 cyc
            dly = fmaf(dly, 1.0000001f, 0.0000001f);
        asm volatile("" :: "f"(dly));                // keep the chain alive
    }

    // ================= recurrent phase (byte-identical to R5) ================
    float4 v = up[N_CTX];
    float xp[4];
#pragma unroll
    for (int k = 0; k < 4; k++)
        xp[k] = fmaf(wi[k][0], v.x, fmaf(wi[k][1], v.y, bb[k]));

#pragma unroll 2
    for (int t = N_CTX; t < T_TOTAL; t++) {
        float4 vn = up[(t + 1 < T_TOTAL) ? (t + 1) : t];
        const float hi0 = h0, hi1 = h1;

        float gi  = fmaf(wh[0][0], hi0, fmaf(wh[0][1], hi1, xp[0]));
        float gf  = fmaf(wh[1][0], hi0, fmaf(wh[1][1], hi1, xp[1]));
        float gg2 = fmaf(wh[2][0], hi0, fmaf(wh[2][1], hi1, xp[2]));
        float go  = fmaf(wh[3][0], hi0, fmaf(wh[3][1], hi1, xp[3]));

        float ti = tanh_fast(gi);
        float tf = tanh_fast(gf);
        float tg = tanh_fast(gg2);
        float to = tanh_fast(go);

        float ca = fmaf(tf, c, c);
        float cb = fmaf(ti, tg, tg);
        c = fmaf(0.5f, ca, 0.5f * cb);

        float tc = tanh_fast(c);
        float s  = fmaf(to, tc, tc);

        float p0 = wr0 * s;
        float p1 = wr1 * s;
#pragma unroll
        for (int k = 1; k < TPE; k <<= 1) {
            p0 += __shfl_xor_sync(0xffffffffu, p0, k, TPE);
            p1 += __shfl_xor_sync(0xffffffffu, p1, k, TPE);
        }
        h0 = p0; h1 = p1;
        if (j == 0) op[t] = make_float2(p0, p1);

        // next step's x-part (off critical chain)
#pragma unroll
        for (int k = 0; k < 4; k++)
            xp[k] = fmaf(wi[k][0], vn.x, fmaf(wi[k][1], vn.y, bb[k]));
        v = vn;
    }
}

extern "C" void kernel_launch(void* const* d_in, const int* in_sizes, int n_in,
                              void* d_out, int out_size)
{
    const float* u    = (const float*)d_in[0];
    const float* w_ih = (const float*)d_in[1];
    const float* w_hh = (const float*)d_in[2];
    const float* b_ih = (const float*)d_in[3];
    const float* b_hh = (const float*)d_in[4];
    const float* w_hr = (const float*)d_in[5];
    float* out = (float*)d_out;

    const int B = in_sizes[0] / (T_TOTAL * 4);   // 4096
    const int grid = B / EPB;                    // 1024 blocks x 64 threads

    open_lstm_kernel<<<grid, 64>>>(u, w_ih, w_hh, b_ih, b_hh, w_hr, out);
}

// round 13
// speedup vs baseline: 1.0072x; 1.0072x over previous
#include <cuda_runtime.h>

// OpenLSTM: B=4096 sequences, T=1024, HID=16, PROJ=2.
// t < 256 teacher-forced; t >= 256 recurrent.
//
// R13: TPE=8 revisited with ALL the step-code improvements learned since R2:
// folded sigmoids (5 TANH/unit, was 10), 2-deep gate chains via xp precompute,
// staged batch ordering, TU=2 teacher batching, 2 independent units/thread.
// Why: MIO (TANH+SHFL, ~4.7cyc/op shared path) is the measured floor; TPE=8
// packs 4 elem/warp so the butterfly is 3 rounds covering 4 elements ->
// 4.0 MIO instr/element vs TPE=16's 6.5 (floor 130 vs 210 cyc/SMSP-step).
// Chain now ~146cyc (was ~250 in R2). 1024 warps (1.73/SMSP).

#define T_TOTAL 1024
#define N_CTX   256
#define TPE     8     // threads per element
#define EPB     4     // elements per 32-thread block
#define TU      2     // teacher-phase time unroll (x2 units = ILP 4)

__device__ __forceinline__ float tanh_fast(float x) {
    float y;
    asm("tanh.approx.f32 %0, %1;" : "=f"(y) : "f"(x));
    return y;
}

__global__ void __launch_bounds__(32)
open_lstm_kernel(const float* __restrict__ u,     // (B, T, 4)
                 const float* __restrict__ w_ih,  // (64, 2)
                 const float* __restrict__ w_hh,  // (64, 2)
                 const float* __restrict__ b_ih,  // (64)
                 const float* __restrict__ b_hh,  // (64)
                 const float* __restrict__ w_hr,  // (2, 16)
                 float* __restrict__ out)         // (B, T, 2)
{
    const int lane = threadIdx.x;
    const int g    = lane & (TPE - 1);                // 0..7
    const int e    = blockIdx.x * EPB + (lane >> 3);  // element index

    // Units j = g and g+8. sigma(x)=0.5*tanh(0.5x)+0.5 folded: i/f/o gate
    // rows pre-scaled by 0.5; o-path outer 0.5 folded into w_hr.
    float wi[2][4][2], wh[2][4][2], bb[2][4], wr0[2], wr1[2];
#pragma unroll
    for (int uu = 0; uu < 2; uu++) {
        const int j = g + uu * 8;
#pragma unroll
        for (int k = 0; k < 4; k++) {
            const int r = k * 16 + j;
            const float sc = (k == 2) ? 1.0f : 0.5f;
            wi[uu][k][0] = w_ih[r * 2 + 0] * sc;
            wi[uu][k][1] = w_ih[r * 2 + 1] * sc;
            wh[uu][k][0] = w_hh[r * 2 + 0] * sc;
            wh[uu][k][1] = w_hh[r * 2 + 1] * sc;
            bb[uu][k]    = (b_ih[r] + b_hh[r]) * sc;
        }
        wr0[uu] = w_hr[j]      * 0.5f;
        wr1[uu] = w_hr[16 + j] * 0.5f;
    }

    const float4* __restrict__ up = (const float4*)u + (size_t)e * T_TOTAL;
    float2* __restrict__ op       = (float2*)out + (size_t)e * T_TOTAL;

    float c[2] = {0.0f, 0.0f};
    float h0 = 0.0f, h1 = 0.0f;

    // ================= teacher-forced phase, TU=2 (ILP 4 with 2 units) =======
#pragma unroll 1
    for (int t = 0; t < N_CTX; t += TU) {
        float4 vv[TU];
#pragma unroll
        for (int s = 0; s < TU; s++) vv[s] = up[t + s];

        float gg[TU][2][4];
#pragma unroll
        for (int s = 0; s < TU; s++)
#pragma unroll
            for (int uu = 0; uu < 2; uu++)
#pragma unroll
                for (int k = 0; k < 4; k++)
                    gg[s][uu][k] = fmaf(wi[uu][k][0], vv[s].x,
                                   fmaf(wi[uu][k][1], vv[s].y,
                                   fmaf(wh[uu][k][0], vv[s].z,
                                   fmaf(wh[uu][k][1], vv[s].w, bb[uu][k]))));

        float ti[TU][2], tf[TU][2], tg[TU][2], to[TU][2];
#pragma unroll
        for (int s = 0; s < TU; s++)
#pragma unroll
            for (int uu = 0; uu < 2; uu++) {
                ti[s][uu] = tanh_fast(gg[s][uu][0]);
                tf[s][uu] = tanh_fast(gg[s][uu][1]);
                tg[s][uu] = tanh_fast(gg[s][uu][2]);
                to[s][uu] = tanh_fast(gg[s][uu][3]);
            }

        float tc[TU][2];
#pragma unroll
        for (int s = 0; s < TU; s++)
#pragma unroll
            for (int uu = 0; uu < 2; uu++) {
                float ca = fmaf(tf[s][uu], c[uu], c[uu]);          // 2*sig(f)*c
                float cb = fmaf(ti[s][uu], tg[s][uu], tg[s][uu]);  // 2*sig(i)*tanh(g)
                c[uu] = fmaf(0.5f, ca, 0.5f * cb);
                tc[s][uu] = tanh_fast(c[uu]);
            }

        float p0[TU], p1[TU];
#pragma unroll
        for (int s = 0; s < TU; s++) {
            float b00 = fmaf(wr0[0], to[s][0], wr0[0]);   // wr*(1+to)
            float b01 = fmaf(wr0[1], to[s][1], wr0[1]);
            float b10 = fmaf(wr1[0], to[s][0], wr1[0]);
            float b11 = fmaf(wr1[1], to[s][1], wr1[1]);
            p0[s] = fmaf(b01, tc[s][1], b00 * tc[s][0]);
            p1[s] = fmaf(b11, tc[s][1], b10 * tc[s][0]);
        }
        // 3-round butterflies over 8 lanes, interleaved across TU steps
#pragma unroll
        for (int k = 1; k < TPE; k <<= 1) {
#pragma unroll
            for (int s = 0; s < TU; s++) {
                p0[s] += __shfl_xor_sync(0xffffffffu, p0[s], k, TPE);
                p1[s] += __shfl_xor_sync(0xffffffffu, p1[s], k, TPE);
            }
        }
        if (g == 0) {
#pragma unroll
            for (int s = 0; s < TU; s++)
                op[t + s] = make_float2(p0[s], p1[s]);
        }
        h0 = p0[TU - 1];
        h1 = p1[TU - 1];
    }

    // ================= recurrent phase: staged, ILP 2 (two units) ============
    float4 v = up[N_CTX];
    float xp[2][4];
#pragma unroll
    for (int uu = 0; uu < 2; uu++)
#pragma unroll
        for (int k = 0; k < 4; k++)
            xp[uu][k] = fmaf(wi[uu][k][0], v.x, fmaf(wi[uu][k][1], v.y, bb[uu][k]));

#pragma unroll 2
    for (int t = N_CTX; t < T_TOTAL; t++) {
        float4 vn = up[(t + 1 < T_TOTAL) ? (t + 1) : t];
        const float hi0 = h0, hi1 = h1;

        // stage 1: 8 gate FMAs (2-deep chain, ILP 2 units x 4 gates)
        float gg[2][4];
#pragma unroll
        for (int uu = 0; uu < 2; uu++)
#pragma unroll
            for (int k = 0; k < 4; k++)
                gg[uu][k] = fmaf(wh[uu][k][0], hi0,
                            fmaf(wh[uu][k][1], hi1, xp[uu][k]));

        // stage 2: 8 independent gate TANHs
        float ti[2], tf[2], tg[2], to[2];
#pragma unroll
        for (int uu = 0; uu < 2; uu++) {
            ti[uu] = tanh_fast(gg[uu][0]);
            tf[uu] = tanh_fast(gg[uu][1]);
            tg[uu] = tanh_fast(gg[uu][2]);
            to[uu] = tanh_fast(gg[uu][3]);
        }

        // stage 3: c updates (2 parallel chains) + tanh(c) + off-chain coeffs
        float tc[2];
#pragma unroll
        for (int uu = 0; uu < 2; uu++) {
            float ca = fmaf(tf[uu], c[uu], c[uu]);
            float cb = fmaf(ti[uu], tg[uu], tg[uu]);
            c[uu] = fmaf(0.5f, ca, 0.5f * cb);
            tc[uu] = tanh_fast(c[uu]);
        }
        float b00 = fmaf(wr0[0], to[0], wr0[0]);
        float b01 = fmaf(wr0[1], to[1], wr0[1]);
        float b10 = fmaf(wr1[0], to[0], wr1[0]);
        float b11 = fmaf(wr1[1], to[1], wr1[1]);

        // stage 4: per-lane 2-unit projection partials
        float p0 = fmaf(b01, tc[1], b00 * tc[0]);
        float p1 = fmaf(b11, tc[1], b10 * tc[0]);

        // stage 5: 3-round butterfly over the 8 lanes (6 SHFL for 4 elements)
#pragma unroll
        for (int k = 1; k < TPE; k <<= 1) {
            p0 += __shfl_xor_sync(0xffffffffu, p0, k, TPE);
            p1 += __shfl_xor_sync(0xffffffffu, p1, k, TPE);
        }
        h0 = p0; h1 = p1;
        if (g == 0) op[t] = make_float2(p0, p1);

        // stage 6: next step's x-part (off critical chain)
#pragma unroll
        for (int uu = 0; uu < 2; uu++)
#pragma unroll
            for (int k = 0; k < 4; k++)
                xp[uu][k] = fmaf(wi[uu][k][0], vn.x,
                            fmaf(wi[uu][k][1], vn.y, bb[uu][k]));
        v = vn;
    }
}

extern "C" void kernel_launch(void* const* d_in, const int* in_sizes, int n_in,
                              void* d_out, int out_size)
{
    const float* u    = (const float*)d_in[0];
    const float* w_ih = (const float*)d_in[1];
    const float* w_hh = (const float*)d_in[2];
    const float* b_ih = (const float*)d_in[3];
    const float* b_hh = (const float*)d_in[4];
    const float* w_hr = (const float*)d_in[5];
    float* out = (float*)d_out;

    const int B = in_sizes[0] / (T_TOTAL * 4);   // 4096
    const int grid = B / EPB;                    // 1024 blocks x 32 threads

    open_lstm_kernel<<<grid, 32>>>(u, w_ih, w_hh, b_ih, b_hh, w_hr, out);
}

// round 14
// speedup vs baseline: 1.1165x; 1.1086x over previous
#include <cuda_runtime.h>

// OpenLSTM: B=4096 sequences, T=1024, HID=16, PROJ=2.
// t < 256 teacher-forced; t >= 256 recurrent.
//
// R14 = R5 (191.5us best) with loop-overhead surgery; butterfly/TANH
// structure untouched (measured optimal across R9/R10/R13):
//  1. predicated @p st.global.v2 via inline PTX (ptxas emits BSSY/BSYNC
//     ~37cyc/step for if(j==0){store} -- quickref "patterns absent").
//  2. hc-trick: state hc=c/2 -> c ready 4cyc earlier, hc update off-chain.
//  3. recurrent unrolled in blocks of 4: loads + next-steps' xp batched as
//     independent filler; clamp only in 4-step epilogue.
// Layout: TPE=16, 2 elem/warp, 2048 warps (3.46/SMSP). Folded sigmoids.

#define T_TOTAL 1024
#define N_CTX   256
#define TPE     16
#define EPB     4     // elements per 64-thread block
#define TU      4     // teacher-phase time unroll
#define RU      4     // recurrent block unroll

__device__ __forceinline__ float tanh_fast(float x) {
    float y;
    asm("tanh.approx.f32 %0, %1;" : "=f"(y) : "f"(x));
    return y;
}

// Branch-free predicated 8-byte store: @p st.global.v2.f32 (no BSSY/BSYNC).
__device__ __forceinline__ void store2_if(int j, float2* addr, float a, float b) {
    asm volatile(
        "{ .reg .pred p; setp.eq.s32 p, %0, 0; @p st.global.v2.f32 [%1], {%2, %3}; }"
        :: "r"(j), "l"(addr), "f"(a), "f"(b) : "memory");
}

__global__ void __launch_bounds__(64)
open_lstm_kernel(const float* __restrict__ u,     // (B, T, 4)
                 const float* __restrict__ w_ih,  // (64, 2)
                 const float* __restrict__ w_hh,  // (64, 2)
                 const float* __restrict__ b_ih,  // (64)
                 const float* __restrict__ b_hh,  // (64)
                 const float* __restrict__ w_hr,  // (2, 16)
                 float* __restrict__ out)         // (B, T, 2)
{
    const int tid  = threadIdx.x;
    const int j    = tid & (TPE - 1);                 // hidden unit 0..15
    const int e    = blockIdx.x * EPB + (tid >> 4);   // element index

    // Weights for unit j. sigma(x)=0.5*tanh(0.5x)+0.5 folded: i/f/o gate rows
    // pre-scaled by 0.5; o-path outer 0.5 folded into w_hr.
    float wi[4][2], wh[4][2], bb[4], wr0, wr1;
#pragma unroll
    for (int k = 0; k < 4; k++) {
        const int r = k * 16 + j;
        const float sc = (k == 2) ? 1.0f : 0.5f;
        wi[k][0] = w_ih[r * 2 + 0] * sc;
        wi[k][1] = w_ih[r * 2 + 1] * sc;
        wh[k][0] = w_hh[r * 2 + 0] * sc;
        wh[k][1] = w_hh[r * 2 + 1] * sc;
        bb[k]    = (b_ih[r] + b_hh[r]) * sc;
    }
    wr0 = w_hr[j]      * 0.5f;
    wr1 = w_hr[16 + j] * 0.5f;

    const float4* __restrict__ up = (const float4*)u + (size_t)e * T_TOTAL;
    float2* __restrict__ op       = (float2*)out + (size_t)e * T_TOTAL;

    float hc = 0.0f;               // c/2 (state)
    float h0 = 0.0f, h1 = 0.0f;

    // ================= teacher-forced phase, unrolled x4 =================
#pragma unroll 1
    for (int t = 0; t < N_CTX; t += TU) {
        float4 vv[TU];
#pragma unroll
        for (int s = 0; s < TU; s++) vv[s] = up[t + s];

        float gg[TU][4];
#pragma unroll
        for (int s = 0; s < TU; s++)
#pragma unroll
            for (int k = 0; k < 4; k++)
                gg[s][k] = fmaf(wi[k][0], vv[s].x,
                           fmaf(wi[k][1], vv[s].y,
                           fmaf(wh[k][0], vv[s].z,
                           fmaf(wh[k][1], vv[s].w, bb[k]))));

        float ti[TU], tf[TU], tg[TU], to[TU];
#pragma unroll
        for (int s = 0; s < TU; s++) {
            ti[s] = tanh_fast(gg[s][0]);
            tf[s] = tanh_fast(gg[s][1]);
            tg[s] = tanh_fast(gg[s][2]);
            to[s] = tanh_fast(gg[s][3]);
        }

        float tc[TU];
#pragma unroll
        for (int s = 0; s < TU; s++) {
            float ca = fmaf(tf[s], hc, hc);          // sigma(f)*c
            float cb = fmaf(ti[s], tg[s], tg[s]);    // 2*sigma(i)*tanh(g)
            float cf = fmaf(0.5f, cb, ca);           // new c
            tc[s] = tanh_fast(cf);
            hc = 0.5f * cf;                          // off-chain state update
        }

        float p0[TU], p1[TU];
#pragma unroll
        for (int s = 0; s < TU; s++) {
            float b0 = fmaf(wr0, to[s], wr0);        // wr0*(1+to)
            float b1 = fmaf(wr1, to[s], wr1);
            p0[s] = b0 * tc[s];
            p1[s] = b1 * tc[s];
        }
#pragma unroll
        for (int k = 1; k < TPE; k <<= 1) {
#pragma unroll
            for (int s = 0; s < TU; s++) {
                p0[s] += __shfl_xor_sync(0xffffffffu, p0[s], k, TPE);
                p1[s] += __shfl_xor_sync(0xffffffffu, p1[s], k, TPE);
            }
        }
#pragma unroll
        for (int s = 0; s < TU; s++)
            store2_if(j, op + (t + s), p0[s], p1[s]);
        h0 = p0[TU - 1];
        h1 = p1[TU - 1];
    }

    // ================= recurrent phase: blocks of RU=4 =================
    // xp for the first recurrent step
    float xp[4];
    {
        float4 v0 = up[N_CTX];
#pragma unroll
        for (int k = 0; k < 4; k++)
            xp[k] = fmaf(wi[k][0], v0.x, fmaf(wi[k][1], v0.y, bb[k]));
    }

#pragma unroll 1
    for (int t = N_CTX; t < T_TOTAL - RU; t += RU) {
        // batched loads for steps t+1 .. t+RU (always in range here)
        float4 vn[RU];
#pragma unroll
        for (int s = 0; s < RU; s++) vn[s] = up[t + 1 + s];

        // batched xp for the NEXT RU steps (independent of h -> filler work).
        // xpn[s] is consumed by sub-step s+1; xpn[RU-1] carries to next block.
        float xpn[RU][4];
#pragma unroll
        for (int s = 0; s < RU; s++)
#pragma unroll
            for (int k = 0; k < 4; k++)
                xpn[s][k] = fmaf(wi[k][0], vn[s].x,
                            fmaf(wi[k][1], vn[s].y, bb[k]));

#pragma unroll
        for (int s = 0; s < RU; s++) {
            const float* xps = (s == 0) ? xp : xpn[s - 1];

            float gi  = fmaf(wh[0][0], h0, fmaf(wh[0][1], h1, xps[0]));
            float gf  = fmaf(wh[1][0], h0, fmaf(wh[1][1], h1, xps[1]));
            float gg2 = fmaf(wh[2][0], h0, fmaf(wh[2][1], h1, xps[2]));
            float go  = fmaf(wh[3][0], h0, fmaf(wh[3][1], h1, xps[3]));

            float ti = tanh_fast(gi);
            float tf = tanh_fast(gf);
            float tg = tanh_fast(gg2);
            float to = tanh_fast(go);

            float ca = fmaf(tf, hc, hc);             // sigma(f)*c
            float cb = fmaf(ti, tg, tg);             // 2*sigma(i)*tanh(g)
            float cf = fmaf(0.5f, cb, ca);           // new c (8cyc after TANH)
            float tc = tanh_fast(cf);
            hc = 0.5f * cf;                          // off-chain

            float b0 = fmaf(wr0, to, wr0);           // off-chain during tanh
            float b1 = fmaf(wr1, to, wr1);

            float p0 = b0 * tc;
            float p1 = b1 * tc;
#pragma unroll
            for (int k = 1; k < TPE; k <<= 1) {
                p0 += __shfl_xor_sync(0xffffffffu, p0, k, TPE);
                p1 += __shfl_xor_sync(0xffffffffu, p1, k, TPE);
            }
            h0 = p0; h1 = p1;
            store2_if(j, op + (t + s), p0, p1);
        }
        // carry xp for the first sub-step of the next block
#pragma unroll
        for (int k = 0; k < 4; k++) xp[k] = xpn[RU - 1][k];
    }

    // -------- epilogue: last RU steps, clamped prefetch --------
#pragma unroll 1
    for (int t = T_TOTAL - RU; t < T_TOTAL; t++) {
        float4 vn = up[(t + 1 < T_TOTAL) ? (t + 1) : t];

        float gi  = fmaf(wh[0][0], h0, fmaf(wh[0][1], h1, xp[0]));
        float gf  = fmaf(wh[1][0], h0, fmaf(wh[1][1], h1, xp[1]));
        float gg2 = fmaf(wh[2][0], h0, fmaf(wh[2][1], h1, xp[2]));
        float go  = fmaf(wh[3][0], h0, fmaf(wh[3][1], h1, xp[3]));

        float ti = tanh_fast(gi);
        float tf = tanh_fast(gf);
        float tg = tanh_fast(gg2);
        float to = tanh_fast(go);

        float ca = fmaf(tf, hc, hc);
        float cb = fmaf(ti, tg, tg);
        float cf = fmaf(0.5f, cb, ca);
        float tc = tanh_fast(cf);
        hc = 0.5f * cf;

        float b0 = fmaf(wr0, to, wr0);
        float b1 = fmaf(wr1, to, wr1);

        float p0 = b0 * tc;
        float p1 = b1 * tc;
#pragma unroll
        for (int k = 1; k < TPE; k <<= 1) {
            p0 += __shfl_xor_sync(0xffffffffu, p0, k, TPE);
            p1 += __shfl_xor_sync(0xffffffffu, p1, k, TPE);
        }
        h0 = p0; h1 = p1;
        store2_if(j, op + t, p0, p1);

#pragma unroll
        for (int k = 0; k < 4; k++)
            xp[k] = fmaf(wi[k][0], vn.x, fmaf(wi[k][1], vn.y, bb[k]));
    }
}

extern "C" void kernel_launch(void* const* d_in, const int* in_sizes, int n_in,
                              void* d_out, int out_size)
{
    const float* u    = (const float*)d_in[0];
    const float* w_ih = (const float*)d_in[1];
    const float* w_hh = (const float*)d_in[2];
    const float* b_ih = (const float*)d_in[3];
    const float* b_hh = (const float*)d_in[4];
    const float* w_hr = (const float*)d_in[5];
    float* out = (float*)d_out;

    const int B = in_sizes[0] / (T_TOTAL * 4);   // 4096
    const int grid = B / EPB;                    // 1024 blocks x 64 threads

    open_lstm_kernel<<<grid, 64>>>(u, w_ih, w_hh, b_ih, b_hh, w_hr, out);
}